// round 1
// baseline (speedup 1.0000x reference)
#include <cuda_runtime.h>

// Analytic bi-Laplacian of f(x) = tanh(x W1^T) W2^T.
// a_h linear in x  =>  sum_{i,j} d^4 f / dx_i^2 dx_j^2
//   = sum_h W2[o,h] * (||W1[h,:]||^2)^2 * tanh''''(a_h)
// tanh''''(u) = 8 t (1 - t^2)(2 - 3 t^2),  t = tanh(u)

#define B_DIM 256
#define D_DIM 16
#define H_DIM 128
#define O_DIM 8

__global__ __launch_bounds__(H_DIM) void bilap_kernel(
    const float* __restrict__ x,    // (256, 16)
    const float* __restrict__ W1,   // (128, 16)
    const float* __restrict__ W2,   // (8, 128)
    float* __restrict__ out)        // (256, 8)
{
    const int b = blockIdx.x;
    const int h = threadIdx.x;  // 0..127

    __shared__ float xs[D_DIM];
    __shared__ float c[H_DIM];

    if (h < D_DIM) xs[h] = x[b * D_DIM + h];
    __syncthreads();

    // a_h = <W1[h,:], x[b,:]>,  s_h = ||W1[h,:]||^2
    float a = 0.f, s = 0.f;
    const float4* w1 = reinterpret_cast<const float4*>(W1 + h * D_DIM);
#pragma unroll
    for (int i = 0; i < 4; i++) {
        float4 w = w1[i];
        a = fmaf(w.x, xs[4 * i + 0], a);
        a = fmaf(w.y, xs[4 * i + 1], a);
        a = fmaf(w.z, xs[4 * i + 2], a);
        a = fmaf(w.w, xs[4 * i + 3], a);
        s = fmaf(w.x, w.x, s);
        s = fmaf(w.y, w.y, s);
        s = fmaf(w.z, w.z, s);
        s = fmaf(w.w, w.w, s);
    }

    float t  = tanhf(a);
    float t2 = t * t;
    float g  = 8.f * t * (1.f - t2) * (2.f - 3.f * t2);  // tanh''''(a)
    c[h] = g * s * s;
    __syncthreads();

    // out[b,o] = <W2[o,:], c[:]>
    if (h < O_DIM) {
        const float* w2 = W2 + h * H_DIM;
        float acc = 0.f;
#pragma unroll 8
        for (int j = 0; j < H_DIM; j++)
            acc = fmaf(w2[j], c[j], acc);
        out[b * O_DIM + h] = acc;
    }
}

extern "C" void kernel_launch(void* const* d_in, const int* in_sizes, int n_in,
                              void* d_out, int out_size) {
    const float* x  = (const float*)d_in[0];   // 256*16
    const float* W1 = (const float*)d_in[1];   // 128*16
    const float* W2 = (const float*)d_in[2];   // 8*128
    float* out = (float*)d_out;                // 256*8
    bilap_kernel<<<B_DIM, H_DIM>>>(x, W1, W2, out);
}

// round 2
// speedup vs baseline: 1.4954x; 1.4954x over previous
#include <cuda_runtime.h>

// Analytic bi-Laplacian of f(x) = tanh(x W1^T) W2^T.
// Pre-activation a_h is linear in x, so
//   sum_{i,j} d^4 f_o / dx_i^2 dx_j^2 = sum_h W2[o,h] * (||W1[h,:]||^2)^2 * tanh''''(a_h)
//   tanh''''(u) = 8 t (1 - t^2)(2 - 3 t^2), t = tanh(u)
//
// One warp per batch row. No shared memory, no block barriers.
// Lane L owns hidden units h = L, L+32, L+64, L+96.

#define B_DIM 256
#define D_DIM 16
#define H_DIM 128
#define O_DIM 8

__global__ __launch_bounds__(128) void bilap_kernel(
    const float* __restrict__ x,    // (256, 16)
    const float* __restrict__ W1,   // (128, 16)
    const float* __restrict__ W2,   // (8, 128)
    float* __restrict__ out)        // (256, 8)
{
    const int warps_per_blk = blockDim.x >> 5;
    const int b    = blockIdx.x * warps_per_blk + (threadIdx.x >> 5); // batch row
    const int lane = threadIdx.x & 31;

    // x row: uniform float4 loads (L1 broadcast within warp)
    const float4* xv = reinterpret_cast<const float4*>(x + b * D_DIM);
    const float4 x0 = xv[0], x1 = xv[1], x2 = xv[2], x3 = xv[3];

    float acc[O_DIM];
#pragma unroll
    for (int o = 0; o < O_DIM; o++) acc[o] = 0.f;

#pragma unroll
    for (int k = 0; k < 4; k++) {
        const int h = lane + 32 * k;
        const float4* w1 = reinterpret_cast<const float4*>(W1 + h * D_DIM);
        const float4 wa = w1[0], wb = w1[1], wc = w1[2], wd = w1[3];

        float a = wa.x * x0.x;
        a = fmaf(wa.y, x0.y, a); a = fmaf(wa.z, x0.z, a); a = fmaf(wa.w, x0.w, a);
        a = fmaf(wb.x, x1.x, a); a = fmaf(wb.y, x1.y, a); a = fmaf(wb.z, x1.z, a); a = fmaf(wb.w, x1.w, a);
        a = fmaf(wc.x, x2.x, a); a = fmaf(wc.y, x2.y, a); a = fmaf(wc.z, x2.z, a); a = fmaf(wc.w, x2.w, a);
        a = fmaf(wd.x, x3.x, a); a = fmaf(wd.y, x3.y, a); a = fmaf(wd.z, x3.z, a); a = fmaf(wd.w, x3.w, a);

        float s = wa.x * wa.x;
        s = fmaf(wa.y, wa.y, s); s = fmaf(wa.z, wa.z, s); s = fmaf(wa.w, wa.w, s);
        s = fmaf(wb.x, wb.x, s); s = fmaf(wb.y, wb.y, s); s = fmaf(wb.z, wb.z, s); s = fmaf(wb.w, wb.w, s);
        s = fmaf(wc.x, wc.x, s); s = fmaf(wc.y, wc.y, s); s = fmaf(wc.z, wc.z, s); s = fmaf(wc.w, wc.w, s);
        s = fmaf(wd.x, wd.x, s); s = fmaf(wd.y, wd.y, s); s = fmaf(wd.z, wd.z, s); s = fmaf(wd.w, wd.w, s);

        const float t  = tanhf(a);
        const float t2 = t * t;
        const float g  = 8.f * t * (1.f - t2) * (2.f - 3.f * t2);  // tanh''''(a)
        const float c  = g * s * s;

#pragma unroll
        for (int o = 0; o < O_DIM; o++)
            acc[o] = fmaf(c, __ldg(W2 + o * H_DIM + h), acc[o]);
    }

    // Butterfly reduction over the warp: 8 independent chains, depth 5.
#pragma unroll
    for (int off = 16; off > 0; off >>= 1) {
#pragma unroll
        for (int o = 0; o < O_DIM; o++)
            acc[o] += __shfl_xor_sync(0xffffffffu, acc[o], off);
    }

    if (lane < O_DIM)
        out[b * O_DIM + lane] = acc[lane];
}

extern "C" void kernel_launch(void* const* d_in, const int* in_sizes, int n_in,
                              void* d_out, int out_size) {
    const float* x  = (const float*)d_in[0];   // 256*16
    const float* W1 = (const float*)d_in[1];   // 128*16
    const float* W2 = (const float*)d_in[2];   // 8*128
    float* out = (float*)d_out;                // 256*8
    // 64 blocks x 128 threads = 256 warps = 256 batch rows, single wave.
    bilap_kernel<<<64, 128>>>(x, W1, W2, out);
}

// round 4
// speedup vs baseline: 1.5529x; 1.0385x over previous
#include <cuda_runtime.h>

// Analytic bi-Laplacian of f(x) = tanh(x W1^T) W2^T.
// a_h linear in x  =>  sum_{i,j} d^4 f_o / dx_i^2 dx_j^2
//   = sum_h W2[o,h] * (||W1[h,:]||^2)^2 * tanh''''(a_h)
// tanh''''(u) = 8 t (1 - t^2)(2 - 3 t^2),  t = tanh(u)
//
// One warp per batch row, no smem, no barriers.
// tanh via t = 1 - 2/(exp(2a)+1) with ex2/rcp approx MUFUs (err ~1e-6,
// saturates correctly at +-1 for large |a|).

#define B_DIM 256
#define D_DIM 16
#define H_DIM 128
#define O_DIM 8

__device__ __forceinline__ float ex2_approx(float x) {
    float r;
    asm("ex2.approx.f32 %0, %1;" : "=f"(r) : "f"(x));
    return r;
}
__device__ __forceinline__ float rcp_approx(float x) {
    float r;
    asm("rcp.approx.f32 %0, %1;" : "=f"(r) : "f"(x));
    return r;
}

__global__ __launch_bounds__(128) void bilap_kernel(
    const float* __restrict__ x,    // (256, 16)
    const float* __restrict__ W1,   // (128, 16)
    const float* __restrict__ W2,   // (8, 128)
    float* __restrict__ out)        // (256, 8)
{
    const int warps_per_blk = blockDim.x >> 5;
    const int b    = blockIdx.x * warps_per_blk + (threadIdx.x >> 5); // batch row
    const int lane = threadIdx.x & 31;

    // x row: uniform float4 loads (L1 broadcast within warp)
    const float4* xv = reinterpret_cast<const float4*>(x + b * D_DIM);
    const float4 x0 = xv[0], x1 = xv[1], x2 = xv[2], x3 = xv[3];

    float acc[O_DIM];
#pragma unroll
    for (int o = 0; o < O_DIM; o++) acc[o] = 0.f;

    const float LOG2E_X2 = 2.8853900817779268f;  // 2*log2(e)

#pragma unroll
    for (int k = 0; k < 4; k++) {
        const int h = lane + 32 * k;
        const float4* w1 = reinterpret_cast<const float4*>(W1 + h * D_DIM);
        const float4 wa = w1[0], wb = w1[1], wc = w1[2], wd = w1[3];

        // two parallel 8-deep chains for a and s, then combine (depth ~9)
        float a0 = wa.x * x0.x, a1 = wc.x * x2.x;
        a0 = fmaf(wa.y, x0.y, a0); a1 = fmaf(wc.y, x2.y, a1);
        a0 = fmaf(wa.z, x0.z, a0); a1 = fmaf(wc.z, x2.z, a1);
        a0 = fmaf(wa.w, x0.w, a0); a1 = fmaf(wc.w, x2.w, a1);
        a0 = fmaf(wb.x, x1.x, a0); a1 = fmaf(wd.x, x3.x, a1);
        a0 = fmaf(wb.y, x1.y, a0); a1 = fmaf(wd.y, x3.y, a1);
        a0 = fmaf(wb.z, x1.z, a0); a1 = fmaf(wd.z, x3.z, a1);
        a0 = fmaf(wb.w, x1.w, a0); a1 = fmaf(wd.w, x3.w, a1);
        const float a = a0 + a1;

        float s0 = wa.x * wa.x, s1 = wc.x * wc.x;
        s0 = fmaf(wa.y, wa.y, s0); s1 = fmaf(wc.y, wc.y, s1);
        s0 = fmaf(wa.z, wa.z, s0); s1 = fmaf(wc.z, wc.z, s1);
        s0 = fmaf(wa.w, wa.w, s0); s1 = fmaf(wc.w, wc.w, s1);
        s0 = fmaf(wb.x, wb.x, s0); s1 = fmaf(wd.x, wd.x, s1);
        s0 = fmaf(wb.y, wb.y, s0); s1 = fmaf(wd.y, wd.y, s1);
        s0 = fmaf(wb.z, wb.z, s0); s1 = fmaf(wd.z, wd.z, s1);
        s0 = fmaf(wb.w, wb.w, s0); s1 = fmaf(wd.w, wd.w, s1);
        const float s = s0 + s1;

        // t = tanh(a) = 1 - 2/(exp(2a)+1); exact saturation for large |a|
        const float e  = ex2_approx(a * LOG2E_X2);
        const float t  = fmaf(-2.f, rcp_approx(e + 1.f), 1.f);
        const float t2 = t * t;
        const float g  = 8.f * t * (1.f - t2) * (2.f - 3.f * t2);  // tanh''''(a)
        const float c  = g * s * s;

#pragma unroll
        for (int o = 0; o < O_DIM; o++)
            acc[o] = fmaf(c, __ldg(W2 + o * H_DIM + h), acc[o]);
    }

    // Butterfly reduction over the warp: 8 independent chains, depth 5.
#pragma unroll
    for (int off = 16; off > 0; off >>= 1) {
#pragma unroll
        for (int o = 0; o < O_DIM; o++)
            acc[o] += __shfl_xor_sync(0xffffffffu, acc[o], off);
    }

    if (lane < O_DIM)
        out[b * O_DIM + lane] = acc[lane];
}

extern "C" void kernel_launch(void* const* d_in, const int* in_sizes, int n_in,
                              void* d_out, int out_size) {
    const float* x  = (const float*)d_in[0];   // 256*16
    const float* W1 = (const float*)d_in[1];   // 128*16
    const float* W2 = (const float*)d_in[2];   // 8*128
    float* out = (float*)d_out;                // 256*8
    // 64 blocks x 128 threads = 256 warps = 256 batch rows, single wave.
    bilap_kernel<<<64, 128>>>(x, W1, W2, out);
}